// round 9
// baseline (speedup 1.0000x reference)
#include <cuda_runtime.h>
#include <cuda_bf16.h>
#include <math.h>

// ---------------- problem constants ----------------
#define M_ATOMS 8192
#define NB      16
#define NPG     512
#define FD      128
#define HD      64
#define DD      16
#define SE      95
#define EH      159
#define TABN2   8192
#define INVD2   59.0f
#define SPAD    20
#define TPAD    20
#define AST     36          // A-tile row stride (32 rows + pad 4)

// ---------------- device scratch ----------------
__device__ float2 d_tab2[TABN2 + 1];
__device__ float d_srcraw[M_ATOMS * DD];
__device__ float d_psum[(M_ATOMS / 32) * DD];   // per-32-atom-block column sums
__device__ float d_shell[M_ATOMS * SE];
__device__ float d_pa[M_ATOMS];

// ---------------- scalar kernel function f(d) ----------------
__device__ __forceinline__ float kerf(float d, float scr,
                                      const float* kw1, const float* kb1,
                                      const float* kw2, const float* kb2) {
    float base = expf(-scr * d) / fmaxf(d, 1e-6f);
    float g0 = d * (1.0f / 5.0f);
    float g1 = d * (1.0f / 40.0f);
    float rbf[8];
#pragma unroll
    for (int r = 0; r < 8; r++) {
        float dc = d - (5.0f + 5.0f * (float)r);
        rbf[r] = expf(-0.04f * dc * dc);
    }
    float out = kb2[0];
#pragma unroll 4
    for (int k = 0; k < 32; k++) {
        float a = kb1[k];
        a = fmaf(g0, kw1[0 * 32 + k], a);
        a = fmaf(g1, kw1[1 * 32 + k], a);
#pragma unroll
        for (int r = 0; r < 8; r++) a = fmaf(rbf[r], kw1[(2 + r) * 32 + k], a);
        float sl = a / (1.0f + expf(-a));
        out = fmaf(sl, kw2[k], out);
    }
    return base * (1.0f + tanhf(out));
}

// ---------------- K0: build float2 lerp table ----------------
__global__ void table_kernel(const float* __restrict__ k_screen,
                             const float* __restrict__ kw1, const float* __restrict__ kb1,
                             const float* __restrict__ kw2, const float* __restrict__ kb2) {
    int i = blockIdx.x * blockDim.x + threadIdx.x;
    if (i > TABN2) return;
    float scr = log1pf(expf(k_screen[0]));
    float f0 = kerf((float)i / INVD2, scr, kw1, kb1, kw2, kb2);
    float f1 = kerf((float)(i + 1) / INVD2, scr, kw1, kb1, kw2, kb2);
    d_tab2[i] = make_float2(f0, f1 - f0);
}

// ---------------- K1: source MLP, 32 atoms/block, 256 blocks ----------------
// smem floats: As[128*36]=4608, hs[32*68]=2176, os[32*20]=640, ps[128], pq[128], mnv[32], rsv[32]
#define SRC_SMEM_FLOATS (4608 + 2176 + 640 + 128 + 128 + 32 + 32)

__global__ __launch_bounds__(256) void src_gemm_kernel(
    const float* __restrict__ x,
    const float* __restrict__ ing, const float* __restrict__ inb,
    const float* __restrict__ w1, const float* __restrict__ b1,
    const float* __restrict__ w2, const float* __restrict__ b2,
    const float* __restrict__ lg, const float* __restrict__ lb) {
    extern __shared__ float sm[];
    float* As  = sm;                 // [128][36] k-major
    float* hs  = As + 4608;          // [32][68]
    float* os  = hs + 2176;          // [32][20]
    float* ps  = os + 640;
    float* pq  = ps + 128;
    float* mnv = pq + 128;
    float* rsv = mnv + 32;

    int t = threadIdx.x;
    int row4 = t >> 2, lane4 = t & 3;   // valid for t < 128 (32 rows x 4 lanes)
    int i0 = blockIdx.x * 32;

    // pass1: row stats (t < 128)
    if (t < 128) {
        const float4* xr = (const float4*)(x + (size_t)(i0 + row4) * FD);
        float s = 0.0f, q = 0.0f;
#pragma unroll
        for (int i = 0; i < 8; i++) {
            float4 v = xr[lane4 + 4 * i];
            s += v.x + v.y + v.z + v.w;
            q += v.x * v.x + v.y * v.y + v.z * v.z + v.w * v.w;
        }
        ps[t] = s; pq[t] = q;
    }
    __syncthreads();
    if (t < 32) {
        float ss = ps[4 * t] + ps[4 * t + 1] + ps[4 * t + 2] + ps[4 * t + 3];
        float qq = pq[4 * t] + pq[4 * t + 1] + pq[4 * t + 2] + pq[4 * t + 3];
        float mn = ss * (1.0f / FD);
        float vr = qq * (1.0f / FD) - mn * mn;
        mnv[t] = mn; rsv[t] = rsqrtf(vr + 1e-5f);
    }
    __syncthreads();

    // pass2: build normalized A (k-major)
    if (t < 128) {
        const float4* xr = (const float4*)(x + (size_t)(i0 + row4) * FD);
        float mn = mnv[row4], rstd = rsv[row4];
#pragma unroll
        for (int i = 0; i < 8; i++) {
            float4 v = xr[lane4 + 4 * i];
            int k0 = (lane4 + 4 * i) * 4;
            As[(k0 + 0) * AST + row4] = (v.x - mn) * rstd * __ldg(&ing[k0 + 0]) + __ldg(&inb[k0 + 0]);
            As[(k0 + 1) * AST + row4] = (v.y - mn) * rstd * __ldg(&ing[k0 + 1]) + __ldg(&inb[k0 + 1]);
            As[(k0 + 2) * AST + row4] = (v.z - mn) * rstd * __ldg(&ing[k0 + 2]) + __ldg(&inb[k0 + 2]);
            As[(k0 + 3) * AST + row4] = (v.w - mn) * rstd * __ldg(&ing[k0 + 3]) + __ldg(&inb[k0 + 3]);
        }
    }
    __syncthreads();

    // GEMM: (32x128) @ (128x64); thread = 2 rows x 4 cols
    int tx = t & 15, ty = t >> 4;
    {
        float acc[2][4];
#pragma unroll
        for (int r = 0; r < 2; r++)
#pragma unroll
            for (int c = 0; c < 4; c++) acc[r][c] = 0.0f;
#pragma unroll 4
        for (int k = 0; k < FD; k++) {
            float2 a = *(const float2*)&As[k * AST + 2 * ty];
            float4 b = __ldg((const float4*)(w1 + k * HD + 4 * tx));
            float av[2] = { a.x, a.y };
            float bv[4] = { b.x, b.y, b.z, b.w };
#pragma unroll
            for (int r = 0; r < 2; r++)
#pragma unroll
                for (int c = 0; c < 4; c++) acc[r][c] = fmaf(av[r], bv[c], acc[r][c]);
        }
        float4 bb = __ldg((const float4*)(b1 + 4 * tx));
        float bv[4] = { bb.x, bb.y, bb.z, bb.w };
#pragma unroll
        for (int r = 0; r < 2; r++) {
            float4 hv;
            float p0 = acc[r][0] + bv[0]; hv.x = p0 / (1.0f + expf(-p0));
            float p1 = acc[r][1] + bv[1]; hv.y = p1 / (1.0f + expf(-p1));
            float p2 = acc[r][2] + bv[2]; hv.z = p2 / (1.0f + expf(-p2));
            float p3 = acc[r][3] + bv[3]; hv.w = p3 / (1.0f + expf(-p3));
            *(float4*)&hs[(2 * ty + r) * 68 + 4 * tx] = hv;
        }
    }
    __syncthreads();

    // layer2: 64 -> 16 (t < 128: 32 rows x 4 lanes x 4 ch)
    if (t < 128) {
        float4 bb = __ldg((const float4*)(b2 + lane4 * 4));
        float accO[4] = { bb.x, bb.y, bb.z, bb.w };
#pragma unroll 4
        for (int k = 0; k < HD; k++) {
            float h = hs[row4 * 68 + k];
            float4 w = __ldg((const float4*)(w2 + k * DD + lane4 * 4));
            accO[0] = fmaf(h, w.x, accO[0]); accO[1] = fmaf(h, w.y, accO[1]);
            accO[2] = fmaf(h, w.z, accO[2]); accO[3] = fmaf(h, w.w, accO[3]);
        }
        *(float4*)&os[row4 * TPAD + lane4 * 4] = make_float4(accO[0], accO[1], accO[2], accO[3]);
    }
    __syncthreads();

    // LN(16)
    if (t < 32) {
        float ss = 0.0f, qq = 0.0f;
#pragma unroll
        for (int c = 0; c < DD; c++) { float v = os[t * TPAD + c]; ss += v; qq += v * v; }
        float mn = ss * (1.0f / DD);
        float vr = qq * (1.0f / DD) - mn * mn;
        mnv[t] = mn; rsv[t] = rsqrtf(vr + 1e-5f);
    }
    __syncthreads();
    if (t < 128) {
        float mn = mnv[row4], rstd = rsv[row4];
        float4 g4 = __ldg((const float4*)(lg + lane4 * 4));
        float4 b4 = __ldg((const float4*)(lb + lane4 * 4));
        float4 o4 = *(const float4*)&os[row4 * TPAD + lane4 * 4];
        float4 y;
        y.x = (o4.x - mn) * rstd * g4.x + b4.x;
        y.y = (o4.y - mn) * rstd * g4.y + b4.y;
        y.z = (o4.z - mn) * rstd * g4.z + b4.z;
        y.w = (o4.w - mn) * rstd * g4.w + b4.w;
        *(float4*)&d_srcraw[(size_t)(i0 + row4) * DD + lane4 * 4] = y;
        *(float4*)&os[row4 * TPAD + lane4 * 4] = y;
    }
    __syncthreads();

    // block partial column sums (deterministic)
    if (t < DD) {
        float sum = 0.0f;
#pragma unroll 8
        for (int r = 0; r < 32; r++) sum += os[r * TPAD + t];
        d_psum[blockIdx.x * DD + t] = sum;
    }
}

// ---------------- K3: pairwise shell statistics (R4-measured config) ----------------
#define GRED4(v) { v += __shfl_down_sync(0xffffffffu, v, 2); \
                   v += __shfl_down_sync(0xffffffffu, v, 1); }

__global__ __launch_bounds__(256, 2) void pair_kernel(const float* __restrict__ pos) {
    __shared__ float sTf[NPG * SPAD];
    __shared__ float px[NPG], py[NPG], pz[NPG];
    __shared__ float msh[DD];
    int g    = blockIdx.x >> 4;
    int blk  = blockIdx.x & 15;
    int t    = threadIdx.x;
    int gbase = g * NPG;

    if (t < DD) {
        float s = 0.0f;
#pragma unroll
        for (int b = 0; b < 16; b++) s += d_psum[(g * 16 + b) * DD + t];
        msh[t] = s * (1.0f / NPG);
    }
    __syncthreads();
    for (int idx = t; idx < NPG * DD; idx += 256) {
        int j = idx >> 4, c = idx & 15;
        sTf[j * SPAD + c] = d_srcraw[(size_t)(gbase + j) * DD + c] - msh[c];
    }
    for (int j = t; j < NPG; j += 256) {
        const float* p = pos + (size_t)(gbase + j) * 3;
        px[j] = p[0]; py[j] = p[1]; pz[j] = p[2];
    }
    __syncthreads();

    int w = t >> 5, lane = t & 31;
    int a = lane >> 3, sub = lane & 7;
    int half = sub >> 2, jsub = sub & 3;
    int li = blk * 32 + w * 4 + a;
    float xi = px[li], yi = py[li], zi = pz[li];
    int c0 = half * 8;

    float am[40];
    float ac[5], ad[5], ad2[5];
#pragma unroll
    for (int c = 0; c < 40; c++) am[c] = 0.0f;
#pragma unroll
    for (int s = 0; s < 5; s++) { ac[s] = 0.f; ad[s] = 0.f; ad2[s] = 0.f; }

#pragma unroll 4
    for (int it = 0; it < 128; it++) {
        int j = jsub + it * 4;
        float dx = px[j] - xi, dy = py[j] - yi, dz = pz[j] - zi;
        float dsq = fmaf(dx, dx, fmaf(dy, dy, fmaf(dz, dz, 1e-12f)));
        float d = sqrtf(dsq);
        float tt = d * INVD2;
        int k = (int)tt; if (k > TABN2 - 1) k = TABN2 - 1;
        float fr = tt - (float)k;
        float2 tv = __ldg(&d_tab2[k]);
        float wv = fmaf(fr, tv.y, tv.x);
        float f5  = (d >= 5.0f)  ? 1.0f : 0.0f;
        float f10 = (d >= 10.0f) ? 1.0f : 0.0f;
        float f20 = (d >= 20.0f) ? 1.0f : 0.0f;
        float f40 = (d >= 40.0f) ? 1.0f : 0.0f;
        float f80 = (d >= 80.0f) ? 1.0f : 0.0f;
        float m0 = f5 - f10, m1 = f10 - f20, m2 = f20 - f40, m3 = f40 - f80, m4 = f80;
        float w0 = wv * m0, w1 = wv * m1, w2 = wv * m2, w3 = wv * m3, w4 = wv * m4;
        float dd = d * d;
        ac[0] += m0; ad[0] = fmaf(m0, d, ad[0]); ad2[0] = fmaf(m0, dd, ad2[0]);
        ac[1] += m1; ad[1] = fmaf(m1, d, ad[1]); ad2[1] = fmaf(m1, dd, ad2[1]);
        ac[2] += m2; ad[2] = fmaf(m2, d, ad[2]); ad2[2] = fmaf(m2, dd, ad2[2]);
        ac[3] += m3; ad[3] = fmaf(m3, d, ad[3]); ad2[3] = fmaf(m3, dd, ad2[3]);
        ac[4] += m4; ad[4] = fmaf(m4, d, ad[4]); ad2[4] = fmaf(m4, dd, ad2[4]);
        float4 s0 = *(const float4*)(sTf + j * SPAD + c0);
        float4 s1 = *(const float4*)(sTf + j * SPAD + c0 + 4);
        float sv[8] = { s0.x, s0.y, s0.z, s0.w, s1.x, s1.y, s1.z, s1.w };
#pragma unroll
        for (int c = 0; c < 8; c++) {
            am[0 * 8 + c] = fmaf(w0, sv[c], am[0 * 8 + c]);
            am[1 * 8 + c] = fmaf(w1, sv[c], am[1 * 8 + c]);
            am[2 * 8 + c] = fmaf(w2, sv[c], am[2 * 8 + c]);
            am[3 * 8 + c] = fmaf(w3, sv[c], am[3 * 8 + c]);
            am[4 * 8 + c] = fmaf(w4, sv[c], am[4 * 8 + c]);
        }
    }

#pragma unroll
    for (int s = 0; s < 5; s++) { GRED4(ac[s]); GRED4(ad[s]); GRED4(ad2[s]); }
#pragma unroll
    for (int c = 0; c < 40; c++) { GRED4(am[c]); }

    if (jsub == 0) {
        int i = gbase + li;
        float* o = d_shell + (size_t)i * SE;
#pragma unroll
        for (int s = 0; s < 5; s++) {
            float cnt = ac[s];
            float den = fmaxf(cnt, 1.0f);
            float inv = 1.0f / den;
#pragma unroll
            for (int c = 0; c < 8; c++) o[s * 19 + c0 + c] = am[s * 8 + c] * inv;
            if (half == 0) {
                o[s * 19 + 16] = cnt;
                o[s * 19 + 17] = ad[s] * inv;
                o[s * 19 + 18] = sqrtf(ad2[s] * inv + 1e-12f);
            }
        }
    }
}

// ---------------- K4: energy head, 32 atoms/block, 256 blocks ----------------
// smem floats: As[159*36]=5724, hs[32*68]=2176, sc/es/part[32*20]=640 each,
// ps[128], pq[128], 6x32
#define EGY_SMEM_FLOATS (5724 + 2176 + 640 + 640 + 640 + 128 + 128 + 32 * 6)

__global__ __launch_bounds__(256) void energy_gemm_kernel(
    const float* __restrict__ seg, const float* __restrict__ seb,
    const float* __restrict__ sw1, const float* __restrict__ sb1,
    const float* __restrict__ sw2, const float* __restrict__ sb2,
    const float* __restrict__ eg,  const float* __restrict__ ebv,
    const float* __restrict__ ew1, const float* __restrict__ eb1,
    const float* __restrict__ ew2, const float* __restrict__ eb2,
    const float* __restrict__ far_gate, const float* __restrict__ escale) {
    extern __shared__ float sm[];
    float* As   = sm;               // [159][36]
    float* hs   = As + 5724;        // [32][68]
    float* sc   = hs + 2176;
    float* es   = sc + 640;
    float* part = es + 640;
    float* ps   = part + 640;
    float* pq   = ps + 128;
    float* sumS = pq + 128;
    float* qS   = sumS + 32;
    float* mnS  = qS + 32;
    float* rsS  = mnS + 32;
    float* mnE  = rsS + 32;
    float* rsE  = mnE + 32;

    int t = threadIdx.x;
    int row4 = t >> 2, lane4 = t & 3;   // valid for t < 128
    int i0 = blockIdx.x * 32;
    int g = i0 >> 9;
    const float* shrow = d_shell + (size_t)(i0 + row4) * SE;

    // shell row stats + centered src tile
    if (t < 128) {
        float s = 0.0f, q = 0.0f;
        for (int i = 0; i < 24; i++) {
            int k = lane4 + 4 * i;
            if (k < SE) { float v = __ldg(&shrow[k]); s += v; q += v * v; }
        }
        ps[t] = s; pq[t] = q;

        float4 sv = __ldg((const float4*)(d_srcraw + (size_t)(i0 + row4) * DD + lane4 * 4));
        float4 gm = make_float4(0.f, 0.f, 0.f, 0.f);
#pragma unroll
        for (int b = 0; b < 16; b++) {
            float4 p = __ldg((const float4*)(d_psum + (g * 16 + b) * DD + lane4 * 4));
            gm.x += p.x; gm.y += p.y; gm.z += p.z; gm.w += p.w;
        }
        sv.x -= gm.x * (1.0f / NPG); sv.y -= gm.y * (1.0f / NPG);
        sv.z -= gm.z * (1.0f / NPG); sv.w -= gm.w * (1.0f / NPG);
        *(float4*)&sc[row4 * TPAD + lane4 * 4] = sv;
    }
    __syncthreads();
    if (t < 32) {
        float ss = ps[4 * t] + ps[4 * t + 1] + ps[4 * t + 2] + ps[4 * t + 3];
        float qq = pq[4 * t] + pq[4 * t + 1] + pq[4 * t + 2] + pq[4 * t + 3];
        sumS[t] = ss; qS[t] = qq;
        float mn = ss * (1.0f / SE);
        float vr = qq * (1.0f / SE) - mn * mn;
        mnS[t] = mn; rsS[t] = rsqrtf(vr + 1e-5f);
    }
    __syncthreads();

    // As1 = LN(shell) with se_ln
    if (t < 128) {
        float mn = mnS[row4], rstd = rsS[row4];
        for (int i = 0; i < 24; i++) {
            int k = lane4 + 4 * i;
            if (k < SE) {
                float v = __ldg(&shrow[k]);
                As[k * AST + row4] = (v - mn) * rstd * __ldg(&seg[k]) + __ldg(&seb[k]);
            }
        }
    }
    __syncthreads();

    int tx = t & 15, ty = t >> 4;
    // GEMM1: (32x95) @ (95x64)
    {
        float acc[2][4];
#pragma unroll
        for (int r = 0; r < 2; r++)
#pragma unroll
            for (int c = 0; c < 4; c++) acc[r][c] = 0.0f;
#pragma unroll 4
        for (int k = 0; k < SE; k++) {
            float2 a = *(const float2*)&As[k * AST + 2 * ty];
            float4 b = __ldg((const float4*)(sw1 + k * HD + 4 * tx));
            float av[2] = { a.x, a.y };
            float bv[4] = { b.x, b.y, b.z, b.w };
#pragma unroll
            for (int r = 0; r < 2; r++)
#pragma unroll
                for (int c = 0; c < 4; c++) acc[r][c] = fmaf(av[r], bv[c], acc[r][c]);
        }
        float4 bb = __ldg((const float4*)(sb1 + 4 * tx));
        float bv[4] = { bb.x, bb.y, bb.z, bb.w };
#pragma unroll
        for (int r = 0; r < 2; r++) {
            float4 hv;
            float p0 = acc[r][0] + bv[0]; hv.x = p0 / (1.0f + expf(-p0));
            float p1 = acc[r][1] + bv[1]; hv.y = p1 / (1.0f + expf(-p1));
            float p2 = acc[r][2] + bv[2]; hv.z = p2 / (1.0f + expf(-p2));
            float p3 = acc[r][3] + bv[3]; hv.w = p3 / (1.0f + expf(-p3));
            *(float4*)&hs[(2 * ty + r) * 68 + 4 * tx] = hv;
        }
    }
    __syncthreads();

    // emb = hid @ sw2 + sb2
    if (t < 128) {
        float4 bb = __ldg((const float4*)(sb2 + lane4 * 4));
        float accO[4] = { bb.x, bb.y, bb.z, bb.w };
#pragma unroll 4
        for (int k = 0; k < HD; k++) {
            float h = hs[row4 * 68 + k];
            float4 w = __ldg((const float4*)(sw2 + k * DD + lane4 * 4));
            accO[0] = fmaf(h, w.x, accO[0]); accO[1] = fmaf(h, w.y, accO[1]);
            accO[2] = fmaf(h, w.z, accO[2]); accO[3] = fmaf(h, w.w, accO[3]);
        }
        *(float4*)&es[row4 * TPAD + lane4 * 4] = make_float4(accO[0], accO[1], accO[2], accO[3]);
    }
    __syncthreads();

    // ein stats
    if (t < 128) {
        float s = 0.0f, q = 0.0f;
#pragma unroll
        for (int cc = 0; cc < 4; cc++) {
            int c = lane4 * 4 + cc;
            float sv = sc[row4 * TPAD + c], ev = es[row4 * TPAD + c];
            float pv = sv * ev, dv = sv - ev;
            s += sv + ev + pv + dv;
            q += sv * sv + ev * ev + pv * pv + dv * dv;
        }
        ps[t] = s; pq[t] = q;
    }
    __syncthreads();
    if (t < 32) {
        float ss = ps[4 * t] + ps[4 * t + 1] + ps[4 * t + 2] + ps[4 * t + 3] + sumS[t];
        float qq = pq[4 * t] + pq[4 * t + 1] + pq[4 * t + 2] + pq[4 * t + 3] + qS[t];
        float mn = ss * (1.0f / EH);
        float vr = qq * (1.0f / EH) - mn * mn;
        mnE[t] = mn; rsE[t] = rsqrtf(vr + 1e-5f);
    }
    __syncthreads();

    // As2 = LN(ein) with eh_ln
    if (t < 128) {
        float mn = mnE[row4], rstd = rsE[row4];
#pragma unroll
        for (int cc = 0; cc < 4; cc++) {
            int c = lane4 * 4 + cc;
            float sv = sc[row4 * TPAD + c], ev = es[row4 * TPAD + c];
            float vals[4] = { sv, ev, sv * ev, sv - ev };
#pragma unroll
            for (int sgm = 0; sgm < 4; sgm++) {
                int k = sgm * 16 + c;
                As[k * AST + row4] = (vals[sgm] - mn) * rstd * __ldg(&eg[k]) + __ldg(&ebv[k]);
            }
        }
        for (int i = 0; i < 24; i++) {
            int kk = lane4 + 4 * i;
            if (kk < SE) {
                int k = 64 + kk;
                float v = __ldg(&shrow[kk]);
                As[k * AST + row4] = (v - mn) * rstd * __ldg(&eg[k]) + __ldg(&ebv[k]);
            }
        }
    }
    __syncthreads();

    // GEMM2: (32x159) @ (159x64), silu, dot ew2
    {
        float acc[2][4];
#pragma unroll
        for (int r = 0; r < 2; r++)
#pragma unroll
            for (int c = 0; c < 4; c++) acc[r][c] = 0.0f;
#pragma unroll 4
        for (int k = 0; k < EH; k++) {
            float2 a = *(const float2*)&As[k * AST + 2 * ty];
            float4 b = __ldg((const float4*)(ew1 + k * HD + 4 * tx));
            float av[2] = { a.x, a.y };
            float bv[4] = { b.x, b.y, b.z, b.w };
#pragma unroll
            for (int r = 0; r < 2; r++)
#pragma unroll
                for (int c = 0; c < 4; c++) acc[r][c] = fmaf(av[r], bv[c], acc[r][c]);
        }
        float4 bb = __ldg((const float4*)(eb1 + 4 * tx));
        float4 w2v = __ldg((const float4*)(ew2 + 4 * tx));
        float bv[4] = { bb.x, bb.y, bb.z, bb.w };
        float wv[4] = { w2v.x, w2v.y, w2v.z, w2v.w };
#pragma unroll
        for (int r = 0; r < 2; r++) {
            float rp = 0.0f;
#pragma unroll
            for (int c = 0; c < 4; c++) {
                float pre = acc[r][c] + bv[c];
                float sl = pre / (1.0f + expf(-pre));
                rp = fmaf(sl, wv[c], rp);
            }
            part[(2 * ty + r) * TPAD + tx] = rp;
        }
    }
    __syncthreads();
    if (t < 32) {
        float s = 0.0f;
#pragma unroll
        for (int k = 0; k < 16; k++) s += part[t * TPAD + k];
        float pa = s + __ldg(&eb2[0]);
        pa *= tanhf(__ldg(&far_gate[0])) * expf(__ldg(&escale[0]));
        d_pa[i0 + t] = pa;
    }
}

// ---------------- K5: per-graph energy sum ----------------
__global__ __launch_bounds__(512) void reduce_kernel(float* __restrict__ out) {
    int g = blockIdx.x;
    int t = threadIdx.x;
    double v = (double)d_pa[g * NPG + t];
#pragma unroll
    for (int o = 16; o; o >>= 1) v += __shfl_xor_sync(0xffffffffu, v, o);
    __shared__ double sd[16];
    if ((t & 31) == 0) sd[t >> 5] = v;
    __syncthreads();
    if (t == 0) {
        double s = 0.0;
#pragma unroll
        for (int k = 0; k < 16; k++) s += sd[k];
        out[g] = (float)s;
    }
}

// ---------------- launcher ----------------
extern "C" void kernel_launch(void* const* d_in, const int* in_sizes, int n_in,
                              void* d_out, int out_size) {
    const float* x   = (const float*)d_in[0];
    const float* pos = (const float*)d_in[1];
    int idx = 3;
    if (idx < n_in && in_sizes[idx] == 1 && in_sizes[idx + 1] == FD) idx++;

    const float* in_ln_g = (const float*)d_in[idx++];
    const float* in_ln_b = (const float*)d_in[idx++];
    const float* src_w1  = (const float*)d_in[idx++];
    const float* src_b1  = (const float*)d_in[idx++];
    const float* src_w2  = (const float*)d_in[idx++];
    const float* src_b2  = (const float*)d_in[idx++];
    const float* src_lng = (const float*)d_in[idx++];
    const float* src_lnb = (const float*)d_in[idx++];
    const float* se_ln_g = (const float*)d_in[idx++];
    const float* se_ln_b = (const float*)d_in[idx++];
    const float* se_w1   = (const float*)d_in[idx++];
    const float* se_b1   = (const float*)d_in[idx++];
    const float* se_w2   = (const float*)d_in[idx++];
    const float* se_b2   = (const float*)d_in[idx++];
    const float* eh_ln_g = (const float*)d_in[idx++];
    const float* eh_ln_b = (const float*)d_in[idx++];
    const float* eh_w1   = (const float*)d_in[idx++];
    const float* eh_b1   = (const float*)d_in[idx++];
    const float* eh_w2   = (const float*)d_in[idx++];
    const float* eh_b2   = (const float*)d_in[idx++];
    const float* k_scr   = (const float*)d_in[idx++];
    const float* kg_w1   = (const float*)d_in[idx++];
    const float* kg_b1   = (const float*)d_in[idx++];
    const float* kg_w2   = (const float*)d_in[idx++];
    const float* kg_b2   = (const float*)d_in[idx++];
    const float* far_g   = (const float*)d_in[idx++];
    const float* e_scale = (const float*)d_in[idx++];

    cudaFuncSetAttribute(src_gemm_kernel, cudaFuncAttributeMaxDynamicSharedMemorySize,
                         SRC_SMEM_FLOATS * 4);
    cudaFuncSetAttribute(energy_gemm_kernel, cudaFuncAttributeMaxDynamicSharedMemorySize,
                         EGY_SMEM_FLOATS * 4);

    table_kernel<<<(TABN2 + 256) / 256, 256>>>(k_scr, kg_w1, kg_b1, kg_w2, kg_b2);
    src_gemm_kernel<<<M_ATOMS / 32, 256, SRC_SMEM_FLOATS * 4>>>(
        x, in_ln_g, in_ln_b, src_w1, src_b1, src_w2, src_b2, src_lng, src_lnb);
    pair_kernel<<<NB * 16, 256>>>(pos);
    energy_gemm_kernel<<<M_ATOMS / 32, 256, EGY_SMEM_FLOATS * 4>>>(
        se_ln_g, se_ln_b, se_w1, se_b1, se_w2, se_b2,
        eh_ln_g, eh_ln_b, eh_w1, eh_b1, eh_w2, eh_b2, far_g, e_scale);
    reduce_kernel<<<NB, 512>>>((float*)d_out);
}

// round 10
// speedup vs baseline: 1.1469x; 1.1469x over previous
#include <cuda_runtime.h>
#include <cuda_bf16.h>
#include <math.h>

// ---------------- problem constants ----------------
#define M_ATOMS 8192
#define NB      16
#define NPG     512
#define FD      128
#define HD      64
#define DD      16
#define SE      95
#define EH      159
#define TABN2   8192
#define INVD2   59.0f
#define SPAD    20
#define TPAD    20
#define AST     36          // 32-row A-tile stride (energy kernel)

// ---------------- device scratch ----------------
__device__ float2 d_tab2[TABN2 + 1];
__device__ float d_srcraw[M_ATOMS * DD];
__device__ float d_psum[(M_ATOMS / 64) * DD];   // per-64-atom-block column sums
__device__ float d_shell[M_ATOMS * SE];
__device__ float d_pa[M_ATOMS];

// ---------------- scalar kernel function f(d) ----------------
__device__ __forceinline__ float kerf(float d, float scr,
                                      const float* kw1, const float* kb1,
                                      const float* kw2, const float* kb2) {
    float base = expf(-scr * d) / fmaxf(d, 1e-6f);
    float g0 = d * (1.0f / 5.0f);
    float g1 = d * (1.0f / 40.0f);
    float rbf[8];
#pragma unroll
    for (int r = 0; r < 8; r++) {
        float dc = d - (5.0f + 5.0f * (float)r);
        rbf[r] = expf(-0.04f * dc * dc);
    }
    float out = kb2[0];
#pragma unroll 4
    for (int k = 0; k < 32; k++) {
        float a = kb1[k];
        a = fmaf(g0, kw1[0 * 32 + k], a);
        a = fmaf(g1, kw1[1 * 32 + k], a);
#pragma unroll
        for (int r = 0; r < 8; r++) a = fmaf(rbf[r], kw1[(2 + r) * 32 + k], a);
        float sl = a / (1.0f + expf(-a));
        out = fmaf(sl, kw2[k], out);
    }
    return base * (1.0f + tanhf(out));
}

// ---------------- K0: build float2 lerp table ----------------
__global__ void table_kernel(const float* __restrict__ k_screen,
                             const float* __restrict__ kw1, const float* __restrict__ kb1,
                             const float* __restrict__ kw2, const float* __restrict__ kb2) {
    int i = blockIdx.x * blockDim.x + threadIdx.x;
    if (i > TABN2) return;
    float scr = log1pf(expf(k_screen[0]));
    float f0 = kerf((float)i / INVD2, scr, kw1, kb1, kw2, kb2);
    float f1 = kerf((float)(i + 1) / INVD2, scr, kw1, kb1, kw2, kb2);
    d_tab2[i] = make_float2(f0, f1 - f0);
}

// ---------------- K1: source MLP, 64 atoms/block (R8-measured version) ----------------
#define SRC_SMEM_FLOATS (8704 + 4352 + 1280 + 256 + 256 + 64 + 64)

__global__ __launch_bounds__(256) void src_gemm_kernel(
    const float* __restrict__ x,
    const float* __restrict__ ing, const float* __restrict__ inb,
    const float* __restrict__ w1, const float* __restrict__ b1,
    const float* __restrict__ w2, const float* __restrict__ b2,
    const float* __restrict__ lg, const float* __restrict__ lb) {
    extern __shared__ float sm[];
    float* As  = sm;
    float* hs  = As + 8704;
    float* os  = hs + 4352;
    float* ps  = os + 1280;
    float* pq  = ps + 256;
    float* mnv = pq + 256;
    float* rsv = mnv + 64;

    int t = threadIdx.x;
    int row4 = t >> 2, lane4 = t & 3;
    int i0 = blockIdx.x * 64;

    // pass1: row stats
    const float4* xr = (const float4*)(x + (size_t)(i0 + row4) * FD);
    float s = 0.0f, q = 0.0f;
#pragma unroll
    for (int i = 0; i < 8; i++) {
        float4 v = xr[lane4 + 4 * i];
        s += v.x + v.y + v.z + v.w;
        q += v.x * v.x + v.y * v.y + v.z * v.z + v.w * v.w;
    }
    ps[t] = s; pq[t] = q;
    __syncthreads();
    if (t < 64) {
        float ss = ps[4 * t] + ps[4 * t + 1] + ps[4 * t + 2] + ps[4 * t + 3];
        float qq = pq[4 * t] + pq[4 * t + 1] + pq[4 * t + 2] + pq[4 * t + 3];
        float mn = ss * (1.0f / FD);
        float vr = qq * (1.0f / FD) - mn * mn;
        mnv[t] = mn; rsv[t] = rsqrtf(vr + 1e-5f);
    }
    __syncthreads();

    // pass2: build normalized A (k-major)
    {
        float mn = mnv[row4], rstd = rsv[row4];
#pragma unroll
        for (int i = 0; i < 8; i++) {
            float4 v = xr[lane4 + 4 * i];
            int k0 = (lane4 + 4 * i) * 4;
            As[(k0 + 0) * 68 + row4] = (v.x - mn) * rstd * __ldg(&ing[k0 + 0]) + __ldg(&inb[k0 + 0]);
            As[(k0 + 1) * 68 + row4] = (v.y - mn) * rstd * __ldg(&ing[k0 + 1]) + __ldg(&inb[k0 + 1]);
            As[(k0 + 2) * 68 + row4] = (v.z - mn) * rstd * __ldg(&ing[k0 + 2]) + __ldg(&inb[k0 + 2]);
            As[(k0 + 3) * 68 + row4] = (v.w - mn) * rstd * __ldg(&ing[k0 + 3]) + __ldg(&inb[k0 + 3]);
        }
    }
    __syncthreads();

    // GEMM: 128 x (64x64), 4x4 tiles
    int tx = t & 15, ty = t >> 4;
    float acc[4][4];
#pragma unroll
    for (int r = 0; r < 4; r++)
#pragma unroll
        for (int c = 0; c < 4; c++) acc[r][c] = 0.0f;
#pragma unroll 4
    for (int k = 0; k < FD; k++) {
        float4 a = *(const float4*)&As[k * 68 + 4 * ty];
        float4 b = __ldg((const float4*)(w1 + k * HD + 4 * tx));
        float av[4] = { a.x, a.y, a.z, a.w };
        float bv[4] = { b.x, b.y, b.z, b.w };
#pragma unroll
        for (int r = 0; r < 4; r++)
#pragma unroll
            for (int c = 0; c < 4; c++) acc[r][c] = fmaf(av[r], bv[c], acc[r][c]);
    }
    {
        float4 bb = __ldg((const float4*)(b1 + 4 * tx));
        float bv[4] = { bb.x, bb.y, bb.z, bb.w };
#pragma unroll
        for (int r = 0; r < 4; r++) {
            float4 hv;
            float p0 = acc[r][0] + bv[0]; hv.x = p0 / (1.0f + expf(-p0));
            float p1 = acc[r][1] + bv[1]; hv.y = p1 / (1.0f + expf(-p1));
            float p2 = acc[r][2] + bv[2]; hv.z = p2 / (1.0f + expf(-p2));
            float p3 = acc[r][3] + bv[3]; hv.w = p3 / (1.0f + expf(-p3));
            *(float4*)&hs[(4 * ty + r) * 68 + 4 * tx] = hv;
        }
    }
    __syncthreads();

    // layer2: 64 -> 16
    {
        float4 bb = __ldg((const float4*)(b2 + lane4 * 4));
        float accO[4] = { bb.x, bb.y, bb.z, bb.w };
#pragma unroll 4
        for (int k = 0; k < HD; k++) {
            float h = hs[row4 * 68 + k];
            float4 w = __ldg((const float4*)(w2 + k * DD + lane4 * 4));
            accO[0] = fmaf(h, w.x, accO[0]); accO[1] = fmaf(h, w.y, accO[1]);
            accO[2] = fmaf(h, w.z, accO[2]); accO[3] = fmaf(h, w.w, accO[3]);
        }
        *(float4*)&os[row4 * TPAD + lane4 * 4] = make_float4(accO[0], accO[1], accO[2], accO[3]);
    }
    __syncthreads();

    // LN(16)
    if (t < 64) {
        float ss = 0.0f, qq = 0.0f;
#pragma unroll
        for (int c = 0; c < DD; c++) { float v = os[t * TPAD + c]; ss += v; qq += v * v; }
        float mn = ss * (1.0f / DD);
        float vr = qq * (1.0f / DD) - mn * mn;
        mnv[t] = mn; rsv[t] = rsqrtf(vr + 1e-5f);
    }
    __syncthreads();
    {
        float mn = mnv[row4], rstd = rsv[row4];
        float4 g4 = __ldg((const float4*)(lg + lane4 * 4));
        float4 b4 = __ldg((const float4*)(lb + lane4 * 4));
        float4 o4 = *(const float4*)&os[row4 * TPAD + lane4 * 4];
        float4 y;
        y.x = (o4.x - mn) * rstd * g4.x + b4.x;
        y.y = (o4.y - mn) * rstd * g4.y + b4.y;
        y.z = (o4.z - mn) * rstd * g4.z + b4.z;
        y.w = (o4.w - mn) * rstd * g4.w + b4.w;
        *(float4*)&d_srcraw[(size_t)(i0 + row4) * DD + lane4 * 4] = y;
        __syncthreads();
        *(float4*)&os[row4 * TPAD + lane4 * 4] = y;
    }
    __syncthreads();

    // block partial column sums (64 atoms, deterministic)
    if (t < DD) {
        float sum = 0.0f;
#pragma unroll 8
        for (int r = 0; r < 64; r++) sum += os[r * TPAD + t];
        d_psum[blockIdx.x * DD + t] = sum;
    }
}

// ---------------- K3: pairwise shell statistics (measured config) ----------------
#define GRED4(v) { v += __shfl_down_sync(0xffffffffu, v, 2); \
                   v += __shfl_down_sync(0xffffffffu, v, 1); }

__global__ __launch_bounds__(256, 2) void pair_kernel(const float* __restrict__ pos) {
    __shared__ float sTf[NPG * SPAD];
    __shared__ float px[NPG], py[NPG], pz[NPG];
    __shared__ float msh[DD];
    int g    = blockIdx.x >> 4;
    int blk  = blockIdx.x & 15;
    int t    = threadIdx.x;
    int gbase = g * NPG;

    if (t < DD) {
        float s = 0.0f;
#pragma unroll
        for (int b = 0; b < 8; b++) s += d_psum[(g * 8 + b) * DD + t];
        msh[t] = s * (1.0f / NPG);
    }
    __syncthreads();
    for (int idx = t; idx < NPG * DD; idx += 256) {
        int j = idx >> 4, c = idx & 15;
        sTf[j * SPAD + c] = d_srcraw[(size_t)(gbase + j) * DD + c] - msh[c];
    }
    for (int j = t; j < NPG; j += 256) {
        const float* p = pos + (size_t)(gbase + j) * 3;
        px[j] = p[0]; py[j] = p[1]; pz[j] = p[2];
    }
    __syncthreads();

    int w = t >> 5, lane = t & 31;
    int a = lane >> 3, sub = lane & 7;
    int half = sub >> 2, jsub = sub & 3;
    int li = blk * 32 + w * 4 + a;
    float xi = px[li], yi = py[li], zi = pz[li];
    int c0 = half * 8;

    float am[40];
    float ac[5], ad[5], ad2[5];
#pragma unroll
    for (int c = 0; c < 40; c++) am[c] = 0.0f;
#pragma unroll
    for (int s = 0; s < 5; s++) { ac[s] = 0.f; ad[s] = 0.f; ad2[s] = 0.f; }

#pragma unroll 4
    for (int it = 0; it < 128; it++) {
        int j = jsub + it * 4;
        float dx = px[j] - xi, dy = py[j] - yi, dz = pz[j] - zi;
        float dsq = fmaf(dx, dx, fmaf(dy, dy, fmaf(dz, dz, 1e-12f)));
        float d = sqrtf(dsq);
        float tt = d * INVD2;
        int k = (int)tt; if (k > TABN2 - 1) k = TABN2 - 1;
        float fr = tt - (float)k;
        float2 tv = __ldg(&d_tab2[k]);
        float wv = fmaf(fr, tv.y, tv.x);
        float f5  = (d >= 5.0f)  ? 1.0f : 0.0f;
        float f10 = (d >= 10.0f) ? 1.0f : 0.0f;
        float f20 = (d >= 20.0f) ? 1.0f : 0.0f;
        float f40 = (d >= 40.0f) ? 1.0f : 0.0f;
        float f80 = (d >= 80.0f) ? 1.0f : 0.0f;
        float m0 = f5 - f10, m1 = f10 - f20, m2 = f20 - f40, m3 = f40 - f80, m4 = f80;
        float w0 = wv * m0, w1 = wv * m1, w2 = wv * m2, w3 = wv * m3, w4 = wv * m4;
        float dd = d * d;
        ac[0] += m0; ad[0] = fmaf(m0, d, ad[0]); ad2[0] = fmaf(m0, dd, ad2[0]);
        ac[1] += m1; ad[1] = fmaf(m1, d, ad[1]); ad2[1] = fmaf(m1, dd, ad2[1]);
        ac[2] += m2; ad[2] = fmaf(m2, d, ad[2]); ad2[2] = fmaf(m2, dd, ad2[2]);
        ac[3] += m3; ad[3] = fmaf(m3, d, ad[3]); ad2[3] = fmaf(m3, dd, ad2[3]);
        ac[4] += m4; ad[4] = fmaf(m4, d, ad[4]); ad2[4] = fmaf(m4, dd, ad2[4]);
        float4 s0 = *(const float4*)(sTf + j * SPAD + c0);
        float4 s1 = *(const float4*)(sTf + j * SPAD + c0 + 4);
        float sv[8] = { s0.x, s0.y, s0.z, s0.w, s1.x, s1.y, s1.z, s1.w };
#pragma unroll
        for (int c = 0; c < 8; c++) {
            am[0 * 8 + c] = fmaf(w0, sv[c], am[0 * 8 + c]);
            am[1 * 8 + c] = fmaf(w1, sv[c], am[1 * 8 + c]);
            am[2 * 8 + c] = fmaf(w2, sv[c], am[2 * 8 + c]);
            am[3 * 8 + c] = fmaf(w3, sv[c], am[3 * 8 + c]);
            am[4 * 8 + c] = fmaf(w4, sv[c], am[4 * 8 + c]);
        }
    }

#pragma unroll
    for (int s = 0; s < 5; s++) { GRED4(ac[s]); GRED4(ad[s]); GRED4(ad2[s]); }
#pragma unroll
    for (int c = 0; c < 40; c++) { GRED4(am[c]); }

    if (jsub == 0) {
        int i = gbase + li;
        float* o = d_shell + (size_t)i * SE;
#pragma unroll
        for (int s = 0; s < 5; s++) {
            float cnt = ac[s];
            float den = fmaxf(cnt, 1.0f);
            float inv = 1.0f / den;
#pragma unroll
            for (int c = 0; c < 8; c++) o[s * 19 + c0 + c] = am[s * 8 + c] * inv;
            if (half == 0) {
                o[s * 19 + 16] = cnt;
                o[s * 19 + 17] = ad[s] * inv;
                o[s * 19 + 18] = sqrtf(ad2[s] * inv + 1e-12f);
            }
        }
    }
}

// ---------------- K4: energy head, 32 atoms/block (R9-measured version) ----------------
#define EGY_SMEM_FLOATS (5724 + 2176 + 640 + 640 + 640 + 128 + 128 + 32 * 6)

__global__ __launch_bounds__(256) void energy_gemm_kernel(
    const float* __restrict__ seg, const float* __restrict__ seb,
    const float* __restrict__ sw1, const float* __restrict__ sb1,
    const float* __restrict__ sw2, const float* __restrict__ sb2,
    const float* __restrict__ eg,  const float* __restrict__ ebv,
    const float* __restrict__ ew1, const float* __restrict__ eb1,
    const float* __restrict__ ew2, const float* __restrict__ eb2,
    const float* __restrict__ far_gate, const float* __restrict__ escale) {
    extern __shared__ float sm[];
    float* As   = sm;               // [159][36]
    float* hs   = As + 5724;        // [32][68]
    float* sc   = hs + 2176;
    float* es   = sc + 640;
    float* part = es + 640;
    float* ps   = part + 640;
    float* pq   = ps + 128;
    float* sumS = pq + 128;
    float* qS   = sumS + 32;
    float* mnS  = qS + 32;
    float* rsS  = mnS + 32;
    float* mnE  = rsS + 32;
    float* rsE  = mnE + 32;

    int t = threadIdx.x;
    int row4 = t >> 2, lane4 = t & 3;
    int i0 = blockIdx.x * 32;
    int g = i0 >> 9;
    const float* shrow = d_shell + (size_t)(i0 + row4) * SE;

    // shell row stats + centered src tile
    if (t < 128) {
        float s = 0.0f, q = 0.0f;
        for (int i = 0; i < 24; i++) {
            int k = lane4 + 4 * i;
            if (k < SE) { float v = __ldg(&shrow[k]); s += v; q += v * v; }
        }
        ps[t] = s; pq[t] = q;

        float4 sv = __ldg((const float4*)(d_srcraw + (size_t)(i0 + row4) * DD + lane4 * 4));
        float4 gm = make_float4(0.f, 0.f, 0.f, 0.f);
#pragma unroll
        for (int b = 0; b < 8; b++) {
            float4 p = __ldg((const float4*)(d_psum + (g * 8 + b) * DD + lane4 * 4));
            gm.x += p.x; gm.y += p.y; gm.z += p.z; gm.w += p.w;
        }
        sv.x -= gm.x * (1.0f / NPG); sv.y -= gm.y * (1.0f / NPG);
        sv.z -= gm.z * (1.0f / NPG); sv.w -= gm.w * (1.0f / NPG);
        *(float4*)&sc[row4 * TPAD + lane4 * 4] = sv;
    }
    __syncthreads();
    if (t < 32) {
        float ss = ps[4 * t] + ps[4 * t + 1] + ps[4 * t + 2] + ps[4 * t + 3];
        float qq = pq[4 * t] + pq[4 * t + 1] + pq[4 * t + 2] + pq[4 * t + 3];
        sumS[t] = ss; qS[t] = qq;
        float mn = ss * (1.0f / SE);
        float vr = qq * (1.0f / SE) - mn * mn;
        mnS[t] = mn; rsS[t] = rsqrtf(vr + 1e-5f);
    }
    __syncthreads();

    // As1 = LN(shell) with se_ln
    if (t < 128) {
        float mn = mnS[row4], rstd = rsS[row4];
        for (int i = 0; i < 24; i++) {
            int k = lane4 + 4 * i;
            if (k < SE) {
                float v = __ldg(&shrow[k]);
                As[k * AST + row4] = (v - mn) * rstd * __ldg(&seg[k]) + __ldg(&seb[k]);
            }
        }
    }
    __syncthreads();

    int tx = t & 15, ty = t >> 4;
    // GEMM1: (32x95) @ (95x64)
    {
        float acc[2][4];
#pragma unroll
        for (int r = 0; r < 2; r++)
#pragma unroll
            for (int c = 0; c < 4; c++) acc[r][c] = 0.0f;
#pragma unroll 4
        for (int k = 0; k < SE; k++) {
            float2 a = *(const float2*)&As[k * AST + 2 * ty];
            float4 b = __ldg((const float4*)(sw1 + k * HD + 4 * tx));
            float av[2] = { a.x, a.y };
            float bv[4] = { b.x, b.y, b.z, b.w };
#pragma unroll
            for (int r = 0; r < 2; r++)
#pragma unroll
                for (int c = 0; c < 4; c++) acc[r][c] = fmaf(av[r], bv[c], acc[r][c]);
        }
        float4 bb = __ldg((const float4*)(sb1 + 4 * tx));
        float bv[4] = { bb.x, bb.y, bb.z, bb.w };
#pragma unroll
        for (int r = 0; r < 2; r++) {
            float4 hv;
            float p0 = acc[r][0] + bv[0]; hv.x = p0 / (1.0f + expf(-p0));
            float p1 = acc[r][1] + bv[1]; hv.y = p1 / (1.0f + expf(-p1));
            float p2 = acc[r][2] + bv[2]; hv.z = p2 / (1.0f + expf(-p2));
            float p3 = acc[r][3] + bv[3]; hv.w = p3 / (1.0f + expf(-p3));
            *(float4*)&hs[(2 * ty + r) * 68 + 4 * tx] = hv;
        }
    }
    __syncthreads();

    // emb = hid @ sw2 + sb2
    if (t < 128) {
        float4 bb = __ldg((const float4*)(sb2 + lane4 * 4));
        float accO[4] = { bb.x, bb.y, bb.z, bb.w };
#pragma unroll 4
        for (int k = 0; k < HD; k++) {
            float h = hs[row4 * 68 + k];
            float4 w = __ldg((const float4*)(sw2 + k * DD + lane4 * 4));
            accO[0] = fmaf(h, w.x, accO[0]); accO[1] = fmaf(h, w.y, accO[1]);
            accO[2] = fmaf(h, w.z, accO[2]); accO[3] = fmaf(h, w.w, accO[3]);
        }
        *(float4*)&es[row4 * TPAD + lane4 * 4] = make_float4(accO[0], accO[1], accO[2], accO[3]);
    }
    __syncthreads();

    // ein stats
    if (t < 128) {
        float s = 0.0f, q = 0.0f;
#pragma unroll
        for (int cc = 0; cc < 4; cc++) {
            int c = lane4 * 4 + cc;
            float sv = sc[row4 * TPAD + c], ev = es[row4 * TPAD + c];
            float pv = sv * ev, dv = sv - ev;
            s += sv + ev + pv + dv;
            q += sv * sv + ev * ev + pv * pv + dv * dv;
        }
        ps[t] = s; pq[t] = q;
    }
    __syncthreads();
    if (t < 32) {
        float ss = ps[4 * t] + ps[4 * t + 1] + ps[4 * t + 2] + ps[4 * t + 3] + sumS[t];
        float qq = pq[4 * t] + pq[4 * t + 1] + pq[4 * t + 2] + pq[4 * t + 3] + qS[t];
        float mn = ss * (1.0f / EH);
        float vr = qq * (1.0f / EH) - mn * mn;
        mnE[t] = mn; rsE[t] = rsqrtf(vr + 1e-5f);
    }
    __syncthreads();

    // As2 = LN(ein) with eh_ln
    if (t < 128) {
        float mn = mnE[row4], rstd = rsE[row4];
#pragma unroll
        for (int cc = 0; cc < 4; cc++) {
            int c = lane4 * 4 + cc;
            float sv = sc[row4 * TPAD + c], ev = es[row4 * TPAD + c];
            float vals[4] = { sv, ev, sv * ev, sv - ev };
#pragma unroll
            for (int sgm = 0; sgm < 4; sgm++) {
                int k = sgm * 16 + c;
                As[k * AST + row4] = (vals[sgm] - mn) * rstd * __ldg(&eg[k]) + __ldg(&ebv[k]);
            }
        }
        for (int i = 0; i < 24; i++) {
            int kk = lane4 + 4 * i;
            if (kk < SE) {
                int k = 64 + kk;
                float v = __ldg(&shrow[kk]);
                As[k * AST + row4] = (v - mn) * rstd * __ldg(&eg[k]) + __ldg(&ebv[k]);
            }
        }
    }
    __syncthreads();

    // GEMM2: (32x159) @ (159x64), silu, dot ew2
    {
        float acc[2][4];
#pragma unroll
        for (int r = 0; r < 2; r++)
#pragma unroll
            for (int c = 0; c < 4; c++) acc[r][c] = 0.0f;
#pragma unroll 4
        for (int k = 0; k < EH; k++) {
            float2 a = *(const float2*)&As[k * AST + 2 * ty];
            float4 b = __ldg((const float4*)(ew1 + k * HD + 4 * tx));
            float av[2] = { a.x, a.y };
            float bv[4] = { b.x, b.y, b.z, b.w };
#pragma unroll
            for (int r = 0; r < 2; r++)
#pragma unroll
                for (int c = 0; c < 4; c++) acc[r][c] = fmaf(av[r], bv[c], acc[r][c]);
        }
        float4 bb = __ldg((const float4*)(eb1 + 4 * tx));
        float4 w2v = __ldg((const float4*)(ew2 + 4 * tx));
        float bv[4] = { bb.x, bb.y, bb.z, bb.w };
        float wv[4] = { w2v.x, w2v.y, w2v.z, w2v.w };
#pragma unroll
        for (int r = 0; r < 2; r++) {
            float rp = 0.0f;
#pragma unroll
            for (int c = 0; c < 4; c++) {
                float pre = acc[r][c] + bv[c];
                float sl = pre / (1.0f + expf(-pre));
                rp = fmaf(sl, wv[c], rp);
            }
            part[(2 * ty + r) * TPAD + tx] = rp;
        }
    }
    __syncthreads();
    if (t < 32) {
        float s = 0.0f;
#pragma unroll
        for (int k = 0; k < 16; k++) s += part[t * TPAD + k];
        float pa = s + __ldg(&eb2[0]);
        pa *= tanhf(__ldg(&far_gate[0])) * expf(__ldg(&escale[0]));
        d_pa[i0 + t] = pa;
    }
}

// ---------------- K5: per-graph energy sum ----------------
__global__ __launch_bounds__(512) void reduce_kernel(float* __restrict__ out) {
    int g = blockIdx.x;
    int t = threadIdx.x;
    double v = (double)d_pa[g * NPG + t];
#pragma unroll
    for (int o = 16; o; o >>= 1) v += __shfl_xor_sync(0xffffffffu, v, o);
    __shared__ double sd[16];
    if ((t & 31) == 0) sd[t >> 5] = v;
    __syncthreads();
    if (t == 0) {
        double s = 0.0;
#pragma unroll
        for (int k = 0; k < 16; k++) s += sd[k];
        out[g] = (float)s;
    }
}

// ---------------- launcher ----------------
extern "C" void kernel_launch(void* const* d_in, const int* in_sizes, int n_in,
                              void* d_out, int out_size) {
    const float* x   = (const float*)d_in[0];
    const float* pos = (const float*)d_in[1];
    int idx = 3;
    if (idx < n_in && in_sizes[idx] == 1 && in_sizes[idx + 1] == FD) idx++;

    const float* in_ln_g = (const float*)d_in[idx++];
    const float* in_ln_b = (const float*)d_in[idx++];
    const float* src_w1  = (const float*)d_in[idx++];
    const float* src_b1  = (const float*)d_in[idx++];
    const float* src_w2  = (const float*)d_in[idx++];
    const float* src_b2  = (const float*)d_in[idx++];
    const float* src_lng = (const float*)d_in[idx++];
    const float* src_lnb = (const float*)d_in[idx++];
    const float* se_ln_g = (const float*)d_in[idx++];
    const float* se_ln_b = (const float*)d_in[idx++];
    const float* se_w1   = (const float*)d_in[idx++];
    const float* se_b1   = (const float*)d_in[idx++];
    const float* se_w2   = (const float*)d_in[idx++];
    const float* se_b2   = (const float*)d_in[idx++];
    const float* eh_ln_g = (const float*)d_in[idx++];
    const float* eh_ln_b = (const float*)d_in[idx++];
    const float* eh_w1   = (const float*)d_in[idx++];
    const float* eh_b1   = (const float*)d_in[idx++];
    const float* eh_w2   = (const float*)d_in[idx++];
    const float* eh_b2   = (const float*)d_in[idx++];
    const float* k_scr   = (const float*)d_in[idx++];
    const float* kg_w1   = (const float*)d_in[idx++];
    const float* kg_b1   = (const float*)d_in[idx++];
    const float* kg_w2   = (const float*)d_in[idx++];
    const float* kg_b2   = (const float*)d_in[idx++];
    const float* far_g   = (const float*)d_in[idx++];
    const float* e_scale = (const float*)d_in[idx++];

    cudaFuncSetAttribute(src_gemm_kernel, cudaFuncAttributeMaxDynamicSharedMemorySize,
                         SRC_SMEM_FLOATS * 4);
    cudaFuncSetAttribute(energy_gemm_kernel, cudaFuncAttributeMaxDynamicSharedMemorySize,
                         EGY_SMEM_FLOATS * 4);

    table_kernel<<<(TABN2 + 256) / 256, 256>>>(k_scr, kg_w1, kg_b1, kg_w2, kg_b2);
    src_gemm_kernel<<<M_ATOMS / 64, 256, SRC_SMEM_FLOATS * 4>>>(
        x, in_ln_g, in_ln_b, src_w1, src_b1, src_w2, src_b2, src_lng, src_lnb);
    pair_kernel<<<NB * 16, 256>>>(pos);
    energy_gemm_kernel<<<M_ATOMS / 32, 256, EGY_SMEM_FLOATS * 4>>>(
        se_ln_g, se_ln_b, se_w1, se_b1, se_w2, se_b2,
        eh_ln_g, eh_ln_b, eh_w1, eh_b1, eh_w2, eh_b2, far_g, e_scale);
    reduce_kernel<<<NB, 512>>>((float*)d_out);
}